// round 2
// baseline (speedup 1.0000x reference)
#include <cuda_runtime.h>
#include <cstdint>

#define D_MODEL 512
#define H_HEADS 8
#define HDIM 64
#define B_BATCH 4
#define N_SEQ 8192
#define NI_SEQ 4096
#define NQ_ROWS (B_BATCH * N_SEQ)   // 32768
#define NK_ROWS (B_BATCH * NI_SEQ)  // 16384

// ---------------- scratch (device globals; no allocations allowed) ----------
__device__ float g_Q[NQ_ROWS * D_MODEL];                       // 64 MB
__device__ float g_K[NK_ROWS * D_MODEL];                       // 32 MB (reused per input)
__device__ float g_V[NK_ROWS * D_MODEL];                       // 32 MB (reused per input)
__device__ float g_ksum[3 * B_BATCH * D_MODEL];                // [i][b][512]
__device__ float g_KV[3 * B_BATCH * H_HEADS * HDIM * HDIM];    // [i][b][h][64][64]
__device__ float g_dinv[NQ_ROWS * H_HEADS * 3];                // [row][h][i]

// ---------------- zero small accumulators ----------------------------------
__global__ void zero_small_kernel() {
    int idx = blockIdx.x * 256 + threadIdx.x;
    if (idx < 3 * B_BATCH * H_HEADS * HDIM * HDIM) g_KV[idx] = 0.f;
    if (idx < 3 * B_BATCH * D_MODEL) g_ksum[idx] = 0.f;
}

// ---------------- SGEMM: C[M,N] = A[M,K] @ B[N,K]^T + bias[N] ---------------
// 128x128 tile, BK=8, 8x8 microtile, 256 threads. All dims are multiples.
__global__ __launch_bounds__(256) void sgemm_nt_bias(
    const float* __restrict__ A, const float* __restrict__ B,
    const float* __restrict__ bias, float* __restrict__ C,
    int M, int N, int K)
{
    __shared__ float As[8][128];
    __shared__ float Bs[8][128];
    const int tid = threadIdx.x;
    const int tx = tid & 15;        // 0..15
    const int ty = tid >> 4;        // 0..15
    const int m0 = blockIdx.y * 128;
    const int n0 = blockIdx.x * 128;

    const int lrow = tid >> 1;          // 0..127
    const int lseg = (tid & 1) * 4;     // 0 or 4
    const float* Aptr = A + (size_t)(m0 + lrow) * K + lseg;
    const float* Bptr = B + (size_t)(n0 + lrow) * K + lseg;

    float acc[8][8];
    #pragma unroll
    for (int i = 0; i < 8; i++)
        #pragma unroll
        for (int j = 0; j < 8; j++) acc[i][j] = 0.f;

    for (int k0 = 0; k0 < K; k0 += 8) {
        float4 av = *(const float4*)(Aptr + k0);
        float4 bv = *(const float4*)(Bptr + k0);
        As[lseg + 0][lrow] = av.x; As[lseg + 1][lrow] = av.y;
        As[lseg + 2][lrow] = av.z; As[lseg + 3][lrow] = av.w;
        Bs[lseg + 0][lrow] = bv.x; Bs[lseg + 1][lrow] = bv.y;
        Bs[lseg + 2][lrow] = bv.z; Bs[lseg + 3][lrow] = bv.w;
        __syncthreads();
        #pragma unroll
        for (int kk = 0; kk < 8; kk++) {
            float a[8], b[8];
            *(float4*)&a[0] = *(const float4*)&As[kk][ty * 8];
            *(float4*)&a[4] = *(const float4*)&As[kk][ty * 8 + 4];
            *(float4*)&b[0] = *(const float4*)&Bs[kk][tx * 8];
            *(float4*)&b[4] = *(const float4*)&Bs[kk][tx * 8 + 4];
            #pragma unroll
            for (int i = 0; i < 8; i++)
                #pragma unroll
                for (int j = 0; j < 8; j++)
                    acc[i][j] += a[i] * b[j];
        }
        __syncthreads();
    }

    #pragma unroll
    for (int i = 0; i < 8; i++) {
        float* crow = C + (size_t)(m0 + ty * 8 + i) * N + n0 + tx * 8;
        #pragma unroll
        for (int j = 0; j < 8; j++)
            crow[j] = acc[i][j] + bias[n0 + tx * 8 + j];
    }
}

// ---------------- softmax over each 64-col head chunk; optional row mask ----
// grid = rows, block = 256 (8 warps = 8 head chunks = one full row)
// mask is int32 (harness delivers bool as int32)
__global__ __launch_bounds__(256) void softmax64_kernel(
    float* __restrict__ X, const int* __restrict__ mask, int rows_per_batch)
{
    const int row = blockIdx.x;
    const int h = threadIdx.x >> 5;
    const int lane = threadIdx.x & 31;
    float* p = X + (size_t)row * D_MODEL + h * HDIM;

    if (mask) {
        if (mask[row] == 0) {   // row = b*rows_per_batch + s, mask is [b, ni] flat
            p[lane] = 0.f; p[lane + 32] = 0.f;
            return;
        }
    }
    float v0 = p[lane], v1 = p[lane + 32];
    float m = fmaxf(v0, v1);
    #pragma unroll
    for (int o = 16; o; o >>= 1) m = fmaxf(m, __shfl_xor_sync(0xffffffffu, m, o));
    v0 = expf(v0 - m); v1 = expf(v1 - m);
    float s = v0 + v1;
    #pragma unroll
    for (int o = 16; o; o >>= 1) s += __shfl_xor_sync(0xffffffffu, s, o);
    float inv = 1.f / s;
    p[lane] = v0 * inv; p[lane + 32] = v1 * inv;
}

// ---------------- k_sum: column sum of masked-softmaxed K over s ------------
// grid (b=4, 2 col-strips of 256, 8 row chunks of 512)
__global__ __launch_bounds__(256) void colsum_kernel(int i)
{
    const int b = blockIdx.x;
    const int c = blockIdx.y * 256 + threadIdx.x;
    const int s0 = blockIdx.z * 512;
    const float* p = g_K + ((size_t)b * NI_SEQ + s0) * D_MODEL + c;
    float s = 0.f;
    #pragma unroll 8
    for (int r = 0; r < 512; r++) s += p[(size_t)r * D_MODEL];
    atomicAdd(&g_ksum[(i * B_BATCH + b) * D_MODEL + c], s);
}

// ---------------- kv[i][b][h] = K_h^T @ V_h  (64x64, reduce over ni) --------
// grid (32 = b*h, 8 s-splits of 512), block 256, 4x4 microtile
__global__ __launch_bounds__(256) void kv_kernel(int i)
{
    __shared__ float Ks[32][64];
    __shared__ float Vs[32][64];
    const int bh = blockIdx.x;
    const int b = bh >> 3, h = bh & 7;
    const int s0 = blockIdx.y * 512;
    const int tid = threadIdx.x;
    const int tx = tid & 15, ty = tid >> 4;

    const float* Kbase = g_K + (size_t)b * NI_SEQ * D_MODEL + h * HDIM;
    const float* Vbase = g_V + (size_t)b * NI_SEQ * D_MODEL + h * HDIM;

    float acc[4][4];
    #pragma unroll
    for (int d = 0; d < 4; d++)
        #pragma unroll
        for (int e = 0; e < 4; e++) acc[d][e] = 0.f;

    for (int st = 0; st < 512; st += 32) {
        #pragma unroll
        for (int l = 0; l < 2; l++) {
            int idx = tid + l * 256;          // 0..511 float4 slots
            int r = idx >> 4;
            int c4 = (idx & 15) * 4;
            *(float4*)&Ks[r][c4] = *(const float4*)(Kbase + (size_t)(s0 + st + r) * D_MODEL + c4);
            *(float4*)&Vs[r][c4] = *(const float4*)(Vbase + (size_t)(s0 + st + r) * D_MODEL + c4);
        }
        __syncthreads();
        #pragma unroll 8
        for (int ks = 0; ks < 32; ks++) {
            float a[4], v[4];
            *(float4*)a = *(const float4*)&Ks[ks][ty * 4];
            *(float4*)v = *(const float4*)&Vs[ks][tx * 4];
            #pragma unroll
            for (int d = 0; d < 4; d++)
                #pragma unroll
                for (int e = 0; e < 4; e++)
                    acc[d][e] += a[d] * v[e];
        }
        __syncthreads();
    }
    float* out = g_KV + (size_t)((i * B_BATCH + b) * H_HEADS + h) * (HDIM * HDIM);
    #pragma unroll
    for (int d = 0; d < 4; d++)
        #pragma unroll
        for (int e = 0; e < 4; e++)
            atomicAdd(&out[(ty * 4 + d) * HDIM + tx * 4 + e], acc[d][e]);
}

// ---------------- d_inv[row][h][i] = 1 / dot(q_rowh, ksum_ih) ---------------
// grid 32768 blocks of 256 (8 warps each; warp -> one (row,h))
__global__ __launch_bounds__(256) void dinv_kernel()
{
    const int w = blockIdx.x * 8 + (threadIdx.x >> 5);
    const int lane = threadIdx.x & 31;
    const int row = w >> 3;     // 0..32767 (= b*8192 + n)
    const int h = w & 7;
    const int b = row >> 13;    // /8192
    const float* q = g_Q + (size_t)row * D_MODEL + h * HDIM;
    const float q0 = q[lane], q1 = q[lane + 32];
    float r[3];
    #pragma unroll
    for (int i = 0; i < 3; i++) {
        const float* ks = g_ksum + (i * B_BATCH + b) * D_MODEL + h * HDIM;
        float p = q0 * ks[lane] + q1 * ks[lane + 32];
        #pragma unroll
        for (int o = 16; o; o >>= 1) p += __shfl_xor_sync(0xffffffffu, p, o);
        r[i] = p;
    }
    if (lane == 0) {
        float* o = g_dinv + (size_t)w * 3;
        o[0] = 1.f / r[0]; o[1] = 1.f / r[1]; o[2] = 1.f / r[2];
    }
}

// ---------------- mix: Q <- (q + sum_i (q @ kv_i) * dinv_i) / 3, in place ---
// grid (32 = b*h, 128 row tiles of 64), block 256 (16x16, 4x4 microtile)
// dyn smem: Qs[64][64] + kvs[3][64][64] + dvs[64][3]
#define MIX_SMEM_FLOATS (64 * 64 + 3 * 64 * 64 + 64 * 3)
__global__ __launch_bounds__(256) void mix_kernel()
{
    extern __shared__ float sm[];
    float* Qs  = sm;                      // [64][64] natural layout
    float* kvs = sm + 64 * 64;            // [3][64][64]
    float* dvs = sm + 64 * 64 + 3 * 64 * 64;  // [64][3]

    const int bh = blockIdx.x;
    const int b = bh >> 3, h = bh & 7;
    const int r0 = blockIdx.y * 64;       // row tile within the batch's 8192
    const int tid = threadIdx.x;
    const int tx = tid & 15, ty = tid >> 4;

    // load 64x64 Q tile (head slice), coalesced
    const size_t qbase = ((size_t)b * N_SEQ + r0) * D_MODEL + h * HDIM;
    #pragma unroll
    for (int l = 0; l < 16; l++) {
        int idx = l * 256 + tid;          // 0..4095
        int r = idx >> 6, d = idx & 63;
        Qs[idx] = g_Q[qbase + (size_t)r * D_MODEL + d];
    }
    // load the three kv matrices
    #pragma unroll
    for (int i = 0; i < 3; i++) {
        const float* src = g_KV + (size_t)((i * B_BATCH + b) * H_HEADS + h) * 4096;
        #pragma unroll
        for (int l = 0; l < 16; l++) {
            int idx = l * 256 + tid;
            kvs[i * 4096 + idx] = src[idx];
        }
    }
    // load dinv for the 64 rows
    if (tid < 192) {
        int r = tid / 3, i = tid % 3;
        dvs[tid] = g_dinv[(size_t)(((size_t)b * N_SEQ + r0 + r) * H_HEADS + h) * 3 + i];
    }
    __syncthreads();

    float acc[3][4][4];
    #pragma unroll
    for (int i = 0; i < 3; i++)
        #pragma unroll
        for (int jr = 0; jr < 4; jr++)
            #pragma unroll
            for (int je = 0; je < 4; je++) acc[i][jr][je] = 0.f;

    #pragma unroll 4
    for (int d = 0; d < 64; d++) {
        float a[4];
        #pragma unroll
        for (int jr = 0; jr < 4; jr++) a[jr] = Qs[(ty * 4 + jr) * 64 + d];
        #pragma unroll
        for (int i = 0; i < 3; i++) {
            float bv[4];
            *(float4*)bv = *(const float4*)&kvs[i * 4096 + d * 64 + tx * 4];
            #pragma unroll
            for (int jr = 0; jr < 4; jr++) {
                acc[i][jr][0] += a[jr] * bv[0];
                acc[i][jr][1] += a[jr] * bv[1];
                acc[i][jr][2] += a[jr] * bv[2];
                acc[i][jr][3] += a[jr] * bv[3];
            }
        }
    }

    const float third = 1.f / 3.f;
    #pragma unroll
    for (int jr = 0; jr < 4; jr++) {
        int r = ty * 4 + jr;
        #pragma unroll
        for (int je = 0; je < 4; je++) {
            int e = tx * 4 + je;
            float y = Qs[r * 64 + e];
            #pragma unroll
            for (int i = 0; i < 3; i++) y += acc[i][jr][je] * dvs[r * 3 + i];
            g_Q[qbase + (size_t)r * D_MODEL + e] = y * third;
        }
    }
}

// ---------------- launcher --------------------------------------------------
extern "C" void kernel_launch(void* const* d_in, const int* in_sizes, int n_in,
                              void* d_out, int out_size)
{
    const float* x    = (const float*)d_in[0];
    const float* emb[3] = { (const float*)d_in[1], (const float*)d_in[2], (const float*)d_in[3] };
    const float* Wq = (const float*)d_in[4];
    const float* bq = (const float*)d_in[5];
    const float* Wk = (const float*)d_in[6];
    const float* bk = (const float*)d_in[7];
    const float* Wv = (const float*)d_in[8];
    const float* bv = (const float*)d_in[9];
    const float* Wo = (const float*)d_in[10];
    const float* bo = (const float*)d_in[11];
    const int* mask[3] = { (const int*)d_in[12], (const int*)d_in[13],
                           (const int*)d_in[14] };
    float* out = (float*)d_out;

    float *Qb = nullptr, *Kb = nullptr, *Vb = nullptr;
    cudaGetSymbolAddress((void**)&Qb, g_Q);
    cudaGetSymbolAddress((void**)&Kb, g_K);
    cudaGetSymbolAddress((void**)&Vb, g_V);
    cudaFuncSetAttribute(mix_kernel, cudaFuncAttributeMaxDynamicSharedMemorySize,
                         MIX_SMEM_FLOATS * sizeof(float));

    zero_small_kernel<<<1536, 256>>>();

    // Q = softmax64(x @ Wq^T + bq)
    sgemm_nt_bias<<<dim3(4, 256), 256>>>(x, Wq, bq, Qb, NQ_ROWS, D_MODEL, D_MODEL);
    softmax64_kernel<<<NQ_ROWS, 256>>>(Qb, nullptr, 0);

    for (int i = 0; i < 3; i++) {
        sgemm_nt_bias<<<dim3(4, 128), 256>>>(emb[i], Wk + (size_t)i * D_MODEL * D_MODEL,
                                             bk + i * D_MODEL, Kb, NK_ROWS, D_MODEL, D_MODEL);
        softmax64_kernel<<<NK_ROWS, 256>>>(Kb, mask[i], NI_SEQ);
        sgemm_nt_bias<<<dim3(4, 128), 256>>>(emb[i], Wv + (size_t)i * D_MODEL * D_MODEL,
                                             bv + i * D_MODEL, Vb, NK_ROWS, D_MODEL, D_MODEL);
        colsum_kernel<<<dim3(4, 2, 8), 256>>>(i);
        kv_kernel<<<dim3(32, 8), 256>>>(i);
    }

    dinv_kernel<<<NQ_ROWS, 256>>>();
    mix_kernel<<<dim3(32, 128), 256, MIX_SMEM_FLOATS * sizeof(float)>>>();

    // out = mixed @ Wo^T + bo
    sgemm_nt_bias<<<dim3(4, 256), 256>>>(Qb, Wo, bo, out, NQ_ROWS, D_MODEL, D_MODEL);
}

// round 4
// speedup vs baseline: 2.1898x; 2.1898x over previous
#include <cuda_runtime.h>
#include <cstdint>

#define D_MODEL 512
#define H_HEADS 8
#define HDIM 64
#define B_BATCH 4
#define N_SEQ 8192
#define NI_SEQ 4096
#define NQ_ROWS (B_BATCH * N_SEQ)   // 32768
#define NK_ROWS (B_BATCH * NI_SEQ)  // 16384

// ---------------- scratch (device globals; no allocations allowed) ----------
__device__ float g_Q[NQ_ROWS * D_MODEL];                       // 64 MB
__device__ float g_K[NK_ROWS * D_MODEL];                       // 32 MB (reused per input)
__device__ float g_V[NK_ROWS * D_MODEL];                       // 32 MB (reused per input)
__device__ float g_ksum[3 * B_BATCH * D_MODEL];                // [i][b][512]
__device__ float g_KV[3 * B_BATCH * H_HEADS * HDIM * HDIM];    // [i][b][h][64][64]

// ---------------- zero small accumulators ----------------------------------
__global__ void zero_small_kernel() {
    int idx = blockIdx.x * 256 + threadIdx.x;
    if (idx < 3 * B_BATCH * H_HEADS * HDIM * HDIM) g_KV[idx] = 0.f;
    if (idx < 3 * B_BATCH * D_MODEL) g_ksum[idx] = 0.f;
}

// ---------------- helpers ---------------------------------------------------
__device__ __forceinline__ float to_tf32(float x) {
    float r;
    asm("cvt.rna.tf32.f32 %0, %1;" : "=f"(r) : "f"(x));
    return r;
}

__device__ __forceinline__ void mma_tf32(float* d, const uint32_t* a, const uint32_t* b) {
    asm volatile(
        "mma.sync.aligned.m16n8k8.row.col.f32.tf32.tf32.f32 "
        "{%0,%1,%2,%3}, {%4,%5,%6,%7}, {%8,%9}, {%0,%1,%2,%3};\n"
        : "+f"(d[0]), "+f"(d[1]), "+f"(d[2]), "+f"(d[3])
        : "r"(a[0]), "r"(a[1]), "r"(a[2]), "r"(a[3]), "r"(b[0]), "r"(b[1]));
}

// ---------------- TF32 tensor GEMM: C[M,N] = A[M,K] @ B[N,K]^T + bias[N] ----
// 128x128 tile, BK=16, 256 threads = 8 warps (2x4), warp tile 64x32.
// All dims are exact multiples (M in {16384,32768}, N=K=512).
#define GPAD 136
__global__ __launch_bounds__(256) void tf32gemm_nt_bias(
    const float* __restrict__ A, const float* __restrict__ B,
    const float* __restrict__ bias, float* __restrict__ C,
    int M, int N, int K)
{
    __shared__ float As[16][GPAD];
    __shared__ float Bs[16][GPAD];

    const int tid  = threadIdx.x;
    const int lane = tid & 31;
    const int wid  = tid >> 5;
    const int wm   = wid >> 2;     // 0..1 -> m offset 0/64
    const int wn   = wid & 3;      // 0..3 -> n offset 0/32/64/96
    const int g    = lane >> 2;    // 0..7
    const int c    = lane & 3;     // 0..3
    const int m0 = blockIdx.y * 128;
    const int n0 = blockIdx.x * 128;

    // gmem: 512 float4 per 128x16 tile, 2 per thread. id -> (row=id>>2, kq=(id&3)*4)
    const int ar0 = tid >> 2,          akq0 = (tid & 3) * 4;
    const int ar1 = (tid + 256) >> 2,  akq1 = (tid & 3) * 4;   // same kq pattern
    const float* Aptr0 = A + (size_t)(m0 + ar0) * K + akq0;
    const float* Aptr1 = A + (size_t)(m0 + ar1) * K + akq1;
    const float* Bptr0 = B + (size_t)(n0 + ar0) * K + akq0;
    const float* Bptr1 = B + (size_t)(n0 + ar1) * K + akq1;

    float acc[4][4][4];
    #pragma unroll
    for (int mf = 0; mf < 4; mf++)
        #pragma unroll
        for (int nf = 0; nf < 4; nf++)
            #pragma unroll
            for (int e = 0; e < 4; e++) acc[mf][nf][e] = 0.f;

    float4 ra0 = *(const float4*)(Aptr0);
    float4 ra1 = *(const float4*)(Aptr1);
    float4 rb0 = *(const float4*)(Bptr0);
    float4 rb1 = *(const float4*)(Bptr1);

    for (int k0 = 0; k0 < K; k0 += 16) {
        // store staged tiles to smem with tf32 rounding
        As[akq0 + 0][ar0] = to_tf32(ra0.x); As[akq0 + 1][ar0] = to_tf32(ra0.y);
        As[akq0 + 2][ar0] = to_tf32(ra0.z); As[akq0 + 3][ar0] = to_tf32(ra0.w);
        As[akq1 + 0][ar1] = to_tf32(ra1.x); As[akq1 + 1][ar1] = to_tf32(ra1.y);
        As[akq1 + 2][ar1] = to_tf32(ra1.z); As[akq1 + 3][ar1] = to_tf32(ra1.w);
        Bs[akq0 + 0][ar0] = to_tf32(rb0.x); Bs[akq0 + 1][ar0] = to_tf32(rb0.y);
        Bs[akq0 + 2][ar0] = to_tf32(rb0.z); Bs[akq0 + 3][ar0] = to_tf32(rb0.w);
        Bs[akq1 + 0][ar1] = to_tf32(rb1.x); Bs[akq1 + 1][ar1] = to_tf32(rb1.y);
        Bs[akq1 + 2][ar1] = to_tf32(rb1.z); Bs[akq1 + 3][ar1] = to_tf32(rb1.w);
        __syncthreads();

        if (k0 + 16 < K) {
            ra0 = *(const float4*)(Aptr0 + k0 + 16);
            ra1 = *(const float4*)(Aptr1 + k0 + 16);
            rb0 = *(const float4*)(Bptr0 + k0 + 16);
            rb1 = *(const float4*)(Bptr1 + k0 + 16);
        }

        #pragma unroll
        for (int kf = 0; kf < 2; kf++) {
            const int kb = kf * 8;
            uint32_t afr[4][4], bfr[4][2];
            #pragma unroll
            for (int mf = 0; mf < 4; mf++) {
                const int mb = wm * 64 + mf * 16 + g;
                afr[mf][0] = __float_as_uint(As[kb + c    ][mb]);
                afr[mf][1] = __float_as_uint(As[kb + c    ][mb + 8]);
                afr[mf][2] = __float_as_uint(As[kb + c + 4][mb]);
                afr[mf][3] = __float_as_uint(As[kb + c + 4][mb + 8]);
            }
            #pragma unroll
            for (int nf = 0; nf < 4; nf++) {
                const int nb = wn * 32 + nf * 8 + g;
                bfr[nf][0] = __float_as_uint(Bs[kb + c    ][nb]);
                bfr[nf][1] = __float_as_uint(Bs[kb + c + 4][nb]);
            }
            #pragma unroll
            for (int mf = 0; mf < 4; mf++)
                #pragma unroll
                for (int nf = 0; nf < 4; nf++)
                    mma_tf32(acc[mf][nf], afr[mf], bfr[nf]);
        }
        __syncthreads();
    }

    // epilogue: bias add + store (float2 per fragment row)
    #pragma unroll
    for (int nf = 0; nf < 4; nf++) {
        const int cb = n0 + wn * 32 + nf * 8 + 2 * c;
        const float bv0 = bias[cb], bv1 = bias[cb + 1];
        #pragma unroll
        for (int mf = 0; mf < 4; mf++) {
            const int r0 = m0 + wm * 64 + mf * 16 + g;
            float2 v0 = make_float2(acc[mf][nf][0] + bv0, acc[mf][nf][1] + bv1);
            float2 v1 = make_float2(acc[mf][nf][2] + bv0, acc[mf][nf][3] + bv1);
            *(float2*)(C + (size_t)r0 * N + cb) = v0;
            *(float2*)(C + (size_t)(r0 + 8) * N + cb) = v1;
        }
    }
}

// ---------------- softmax over each 64-col head chunk; optional row mask ----
// grid = rows, block = 256 (8 warps = 8 head chunks = one full row)
// mask is int32 (harness delivers bool as int32)
__global__ __launch_bounds__(256) void softmax64_kernel(
    float* __restrict__ X, const int* __restrict__ mask)
{
    const int row = blockIdx.x;
    const int h = threadIdx.x >> 5;
    const int lane = threadIdx.x & 31;
    float* p = X + (size_t)row * D_MODEL + h * HDIM;

    if (mask) {
        if (mask[row] == 0) {
            p[lane] = 0.f; p[lane + 32] = 0.f;
            return;
        }
    }
    float v0 = p[lane], v1 = p[lane + 32];
    float m = fmaxf(v0, v1);
    #pragma unroll
    for (int o = 16; o; o >>= 1) m = fmaxf(m, __shfl_xor_sync(0xffffffffu, m, o));
    v0 = expf(v0 - m); v1 = expf(v1 - m);
    float s = v0 + v1;
    #pragma unroll
    for (int o = 16; o; o >>= 1) s += __shfl_xor_sync(0xffffffffu, s, o);
    float inv = 1.f / s;
    p[lane] = v0 * inv; p[lane + 32] = v1 * inv;
}

// ---------------- k_sum: column sum of masked-softmaxed K over s ------------
// grid (b=4, 2 col-strips of 256, 32 row chunks of 128)
__global__ __launch_bounds__(256) void colsum_kernel(int i)
{
    const int b = blockIdx.x;
    const int c = blockIdx.y * 256 + threadIdx.x;
    const int s0 = blockIdx.z * 128;
    const float* p = g_K + ((size_t)b * NI_SEQ + s0) * D_MODEL + c;
    float s = 0.f;
    #pragma unroll 8
    for (int r = 0; r < 128; r++) s += p[(size_t)r * D_MODEL];
    atomicAdd(&g_ksum[(i * B_BATCH + b) * D_MODEL + c], s);
}

// ---------------- kv[i][b][h] = K_h^T @ V_h  (64x64, reduce over ni) --------
// grid (32 = b*h, 8 s-splits of 512), block 256, 4x4 microtile
__global__ __launch_bounds__(256) void kv_kernel(int i)
{
    __shared__ float Ks[32][64];
    __shared__ float Vs[32][64];
    const int bh = blockIdx.x;
    const int b = bh >> 3, h = bh & 7;
    const int s0 = blockIdx.y * 512;
    const int tid = threadIdx.x;
    const int tx = tid & 15, ty = tid >> 4;

    const float* Kbase = g_K + (size_t)b * NI_SEQ * D_MODEL + h * HDIM;
    const float* Vbase = g_V + (size_t)b * NI_SEQ * D_MODEL + h * HDIM;

    float acc[4][4];
    #pragma unroll
    for (int d = 0; d < 4; d++)
        #pragma unroll
        for (int e = 0; e < 4; e++) acc[d][e] = 0.f;

    for (int st = 0; st < 512; st += 32) {
        #pragma unroll
        for (int l = 0; l < 2; l++) {
            int idx = tid + l * 256;          // 0..511 float4 slots
            int r = idx >> 4;
            int c4 = (idx & 15) * 4;
            *(float4*)&Ks[r][c4] = *(const float4*)(Kbase + (size_t)(s0 + st + r) * D_MODEL + c4);
            *(float4*)&Vs[r][c4] = *(const float4*)(Vbase + (size_t)(s0 + st + r) * D_MODEL + c4);
        }
        __syncthreads();
        #pragma unroll 8
        for (int ks = 0; ks < 32; ks++) {
            float a[4], v[4];
            *(float4*)a = *(const float4*)&Ks[ks][ty * 4];
            *(float4*)v = *(const float4*)&Vs[ks][tx * 4];
            #pragma unroll
            for (int d = 0; d < 4; d++)
                #pragma unroll
                for (int e = 0; e < 4; e++)
                    acc[d][e] += a[d] * v[e];
        }
        __syncthreads();
    }
    float* out = g_KV + (size_t)((i * B_BATCH + b) * H_HEADS + h) * (HDIM * HDIM);
    #pragma unroll
    for (int d = 0; d < 4; d++)
        #pragma unroll
        for (int e = 0; e < 4; e++)
            atomicAdd(&out[(ty * 4 + d) * HDIM + tx * 4 + e], acc[d][e]);
}

// ---------------- mix: Q <- (q + sum_i (q @ kv_i) * dinv_i) / 3, in place ---
// dinv_i computed in-kernel from ksum. grid (32 = b*h, 128 row tiles of 64),
// block 256 (16x16, 4x4 microtile)
#define MIX_SMEM_FLOATS (64 * 64 + 3 * 64 * 64 + 64 * 3 + 3 * 64)
__global__ __launch_bounds__(256) void mix_kernel()
{
    extern __shared__ float sm[];
    float* Qs  = sm;                              // [64][64]
    float* kvs = sm + 64 * 64;                    // [3][64][64]
    float* dvs = sm + 64 * 64 + 3 * 64 * 64;      // [64][3]
    float* kss = dvs + 64 * 3;                    // [3][64]

    const int bh = blockIdx.x;
    const int b = bh >> 3, h = bh & 7;
    const int r0 = blockIdx.y * 64;
    const int tid = threadIdx.x;
    const int tx = tid & 15, ty = tid >> 4;

    const size_t qbase = ((size_t)b * N_SEQ + r0) * D_MODEL + h * HDIM;
    #pragma unroll
    for (int l = 0; l < 16; l++) {
        int idx = l * 256 + tid;
        int r = idx >> 6, d = idx & 63;
        Qs[idx] = g_Q[qbase + (size_t)r * D_MODEL + d];
    }
    #pragma unroll
    for (int i = 0; i < 3; i++) {
        const float* src = g_KV + (size_t)((i * B_BATCH + b) * H_HEADS + h) * 4096;
        #pragma unroll
        for (int l = 0; l < 16; l++) {
            int idx = l * 256 + tid;
            kvs[i * 4096 + idx] = src[idx];
        }
    }
    if (tid < 192) {   // [i][d]: i = tid>>6, d = tid&63
        int i = tid >> 6, d = tid & 63;
        kss[tid] = g_ksum[(i * B_BATCH + b) * D_MODEL + h * HDIM + d];
    }
    __syncthreads();

    // compute dinv per row: thread t -> row = t>>2, quarter = t&3 (16 dims each)
    {
        const int r = tid >> 2, qq = tid & 3;
        float p0 = 0.f, p1 = 0.f, p2 = 0.f;
        #pragma unroll
        for (int j = 0; j < 16; j++) {
            int d = qq * 16 + j;
            float qv = Qs[r * 64 + d];
            p0 += qv * kss[d];
            p1 += qv * kss[64 + d];
            p2 += qv * kss[128 + d];
        }
        #pragma unroll
        for (int o = 1; o < 4; o <<= 1) {
            p0 += __shfl_xor_sync(0xffffffffu, p0, o);
            p1 += __shfl_xor_sync(0xffffffffu, p1, o);
            p2 += __shfl_xor_sync(0xffffffffu, p2, o);
        }
        if (qq == 0) {
            dvs[r * 3 + 0] = 1.f / p0;
            dvs[r * 3 + 1] = 1.f / p1;
            dvs[r * 3 + 2] = 1.f / p2;
        }
    }
    __syncthreads();

    float acc[3][4][4];
    #pragma unroll
    for (int i = 0; i < 3; i++)
        #pragma unroll
        for (int jr = 0; jr < 4; jr++)
            #pragma unroll
            for (int je = 0; je < 4; je++) acc[i][jr][je] = 0.f;

    #pragma unroll 4
    for (int d = 0; d < 64; d++) {
        float a[4];
        #pragma unroll
        for (int jr = 0; jr < 4; jr++) a[jr] = Qs[(ty * 4 + jr) * 64 + d];
        #pragma unroll
        for (int i = 0; i < 3; i++) {
            float bv[4];
            *(float4*)bv = *(const float4*)&kvs[i * 4096 + d * 64 + tx * 4];
            #pragma unroll
            for (int jr = 0; jr < 4; jr++) {
                acc[i][jr][0] += a[jr] * bv[0];
                acc[i][jr][1] += a[jr] * bv[1];
                acc[i][jr][2] += a[jr] * bv[2];
                acc[i][jr][3] += a[jr] * bv[3];
            }
        }
    }

    const float third = 1.f / 3.f;
    #pragma unroll
    for (int jr = 0; jr < 4; jr++) {
        int r = ty * 4 + jr;
        #pragma unroll
        for (int je = 0; je < 4; je++) {
            int e = tx * 4 + je;
            float y = Qs[r * 64 + e];
            #pragma unroll
            for (int i = 0; i < 3; i++) y += acc[i][jr][je] * dvs[r * 3 + i];
            g_Q[qbase + (size_t)r * D_MODEL + e] = y * third;
        }
    }
}

// ---------------- launcher --------------------------------------------------
extern "C" void kernel_launch(void* const* d_in, const int* in_sizes, int n_in,
                              void* d_out, int out_size)
{
    const float* x    = (const float*)d_in[0];
    const float* emb[3] = { (const float*)d_in[1], (const float*)d_in[2], (const float*)d_in[3] };
    const float* Wq = (const float*)d_in[4];
    const float* bq = (const float*)d_in[5];
    const float* Wk = (const float*)d_in[6];
    const float* bk = (const float*)d_in[7];
    const float* Wv = (const float*)d_in[8];
    const float* bv = (const float*)d_in[9];
    const float* Wo = (const float*)d_in[10];
    const float* bo = (const float*)d_in[11];
    const int* mask[3] = { (const int*)d_in[12], (const int*)d_in[13],
                           (const int*)d_in[14] };
    float* out = (float*)d_out;

    float *Qb = nullptr, *Kb = nullptr, *Vb = nullptr;
    cudaGetSymbolAddress((void**)&Qb, g_Q);
    cudaGetSymbolAddress((void**)&Kb, g_K);
    cudaGetSymbolAddress((void**)&Vb, g_V);
    cudaFuncSetAttribute(mix_kernel, cudaFuncAttributeMaxDynamicSharedMemorySize,
                         MIX_SMEM_FLOATS * sizeof(float));

    zero_small_kernel<<<1536, 256>>>();

    // Q = softmax64(x @ Wq^T + bq)
    tf32gemm_nt_bias<<<dim3(4, 256), 256>>>(x, Wq, bq, Qb, NQ_ROWS, D_MODEL, D_MODEL);
    softmax64_kernel<<<NQ_ROWS, 256>>>(Qb, nullptr);

    for (int i = 0; i < 3; i++) {
        tf32gemm_nt_bias<<<dim3(4, 128), 256>>>(emb[i], Wk + (size_t)i * D_MODEL * D_MODEL,
                                                bk + i * D_MODEL, Kb, NK_ROWS, D_MODEL, D_MODEL);
        softmax64_kernel<<<NK_ROWS, 256>>>(Kb, mask[i]);
        tf32gemm_nt_bias<<<dim3(4, 128), 256>>>(emb[i], Wv + (size_t)i * D_MODEL * D_MODEL,
                                                bv + i * D_MODEL, Vb, NK_ROWS, D_MODEL, D_MODEL);
        colsum_kernel<<<dim3(4, 2, 32), 256>>>(i);
        kv_kernel<<<dim3(32, 8), 256>>>(i);
    }

    mix_kernel<<<dim3(32, 128), 256, MIX_SMEM_FLOATS * sizeof(float)>>>();

    // out = mixed @ Wo^T + bo
    tf32gemm_nt_bias<<<dim3(4, 256), 256>>>(Qb, Wo, bo, out, NQ_ROWS, D_MODEL, D_MODEL);
}

// round 5
// speedup vs baseline: 2.5985x; 1.1866x over previous
#include <cuda_runtime.h>
#include <cstdint>

#define D_MODEL 512
#define H_HEADS 8
#define HDIM 64
#define B_BATCH 4
#define N_SEQ 8192
#define NI_SEQ 4096
#define NQ_ROWS (B_BATCH * N_SEQ)   // 32768
#define NK_ROWS (B_BATCH * NI_SEQ)  // 16384

// ---------------- scratch (device globals; no allocations allowed) ----------
__device__ float g_Q[NQ_ROWS * D_MODEL];                       // 64 MB
__device__ float g_K[NK_ROWS * D_MODEL];                       // 32 MB (reused per input)
__device__ float g_V[NK_ROWS * D_MODEL];                       // 32 MB (reused per input)
__device__ float g_ksum[3 * B_BATCH * D_MODEL];                // [i][b][512]
__device__ float g_KV[3 * B_BATCH * H_HEADS * HDIM * HDIM];    // [i][b][h][64][64]

// ---------------- zero small accumulators ----------------------------------
__global__ void zero_small_kernel() {
    int idx = blockIdx.x * 256 + threadIdx.x;
    if (idx < 3 * B_BATCH * H_HEADS * HDIM * HDIM) g_KV[idx] = 0.f;
    if (idx < 3 * B_BATCH * D_MODEL) g_ksum[idx] = 0.f;
}

// ---------------- helpers ---------------------------------------------------
__device__ __forceinline__ float to_tf32(float x) {
    float r;
    asm("cvt.rna.tf32.f32 %0, %1;" : "=f"(r) : "f"(x));
    return r;
}

__device__ __forceinline__ void mma_tf32(float* d, const uint32_t* a, const uint32_t* b) {
    asm volatile(
        "mma.sync.aligned.m16n8k8.row.col.f32.tf32.tf32.f32 "
        "{%0,%1,%2,%3}, {%4,%5,%6,%7}, {%8,%9}, {%0,%1,%2,%3};\n"
        : "+f"(d[0]), "+f"(d[1]), "+f"(d[2]), "+f"(d[3])
        : "r"(a[0]), "r"(a[1]), "r"(a[2]), "r"(a[3]), "r"(b[0]), "r"(b[1]));
}

__device__ __forceinline__ void cp_async16(uint32_t smem_addr, const void* gptr) {
    asm volatile("cp.async.cg.shared.global [%0], [%1], 16;\n"
                 :: "r"(smem_addr), "l"(gptr));
}
__device__ __forceinline__ void cp_commit() {
    asm volatile("cp.async.commit_group;\n" ::: "memory");
}
template <int N>
__device__ __forceinline__ void cp_wait() {
    asm volatile("cp.async.wait_group %0;\n" :: "n"(N) : "memory");
}

// ---------------- TF32 tensor GEMM: C[M,N] = A[M,K] @ B[N,K]^T + bias[N] ----
// 128x128 tile, BK=16, 3-stage cp.async pipeline, 256 threads = 8 warps (2x4),
// warp tile 64x32. Smem m-major with row pad 20 (conflict-free LDS: banks
// (g*20+c) mod 32 cover all 32). All dims exact multiples.
#define BKT 16
#define ROWPAD 20
#define STG_A (128 * ROWPAD)          // floats per A (or B) region
#define STG_FLOATS (2 * STG_A)        // per stage
#define NSTAGE 3
#define GEMM_SMEM_BYTES (NSTAGE * STG_FLOATS * 4)

__global__ __launch_bounds__(256, 2) void tf32gemm_nt_bias(
    const float* __restrict__ A, const float* __restrict__ B,
    const float* __restrict__ bias, float* __restrict__ C,
    int M, int N, int K)
{
    extern __shared__ float smem[];

    const int tid  = threadIdx.x;
    const int lane = tid & 31;
    const int wid  = tid >> 5;
    const int wm   = wid >> 2;     // 0..1 -> m offset 0/64
    const int wn   = wid & 3;      // 0..3 -> n offset 0/32/64/96
    const int g    = lane >> 2;    // 0..7
    const int c    = lane & 3;     // 0..3
    const int m0 = blockIdx.y * 128;
    const int n0 = blockIdx.x * 128;

    // copy indices: 512 16B segments per 128x16 tile; 2 per thread per matrix
    const int r0 = tid >> 1;                 // rows 0..127 (tid 0..255 -> 2 segs/row? no:)
    // seg id s in 0..511: row = s>>2, k4 = (s&3)*4
    const int sr0 = tid >> 2,          sk0 = (tid & 3) * 4;
    const int sr1 = (tid + 256) >> 2,  sk1 = (tid & 3) * 4;
    (void)r0;
    const float* Ag0 = A + (size_t)(m0 + sr0) * K + sk0;
    const float* Ag1 = A + (size_t)(m0 + sr1) * K + sk1;
    const float* Bg0 = B + (size_t)(n0 + sr0) * K + sk0;
    const float* Bg1 = B + (size_t)(n0 + sr1) * K + sk1;

    uint32_t smem_base = (uint32_t)__cvta_generic_to_shared(smem);
    const uint32_t sa0 = smem_base + (sr0 * ROWPAD + sk0) * 4;
    const uint32_t sa1 = smem_base + (sr1 * ROWPAD + sk1) * 4;
    const uint32_t sb0 = sa0 + STG_A * 4;
    const uint32_t sb1 = sa1 + STG_A * 4;

    const int NT = K / BKT;

    // prologue: stages 0 and 1
    #pragma unroll
    for (int t = 0; t < 2; t++) {
        uint32_t off = (uint32_t)(t * STG_FLOATS * 4);
        int ko = t * BKT;
        cp_async16(sa0 + off, Ag0 + ko);
        cp_async16(sa1 + off, Ag1 + ko);
        cp_async16(sb0 + off, Bg0 + ko);
        cp_async16(sb1 + off, Bg1 + ko);
        cp_commit();
    }

    float acc[4][4][4];
    #pragma unroll
    for (int mf = 0; mf < 4; mf++)
        #pragma unroll
        for (int nf = 0; nf < 4; nf++)
            #pragma unroll
            for (int e = 0; e < 4; e++) acc[mf][nf][e] = 0.f;

    for (int t = 0; t < NT; t++) {
        cp_wait<1>();
        __syncthreads();

        // issue stage t+2
        if (t + 2 < NT) {
            uint32_t off = (uint32_t)(((t + 2) % NSTAGE) * STG_FLOATS * 4);
            int ko = (t + 2) * BKT;
            cp_async16(sa0 + off, Ag0 + ko);
            cp_async16(sa1 + off, Ag1 + ko);
            cp_async16(sb0 + off, Bg0 + ko);
            cp_async16(sb1 + off, Bg1 + ko);
        }
        cp_commit();   // always commit (possibly empty) to keep group count uniform

        const float* Ab = smem + (t % NSTAGE) * STG_FLOATS;
        const float* Bb = Ab + STG_A;

        #pragma unroll
        for (int kf = 0; kf < 2; kf++) {
            const int kb = kf * 8;
            uint32_t afr[4][4], bfr[4][2];
            #pragma unroll
            for (int mf = 0; mf < 4; mf++) {
                const int mr = (wm * 64 + mf * 16 + g) * ROWPAD;
                afr[mf][0] = __float_as_uint(to_tf32(Ab[mr + kb + c]));
                afr[mf][1] = __float_as_uint(to_tf32(Ab[mr + 8 * ROWPAD + kb + c]));
                afr[mf][2] = __float_as_uint(to_tf32(Ab[mr + kb + c + 4]));
                afr[mf][3] = __float_as_uint(to_tf32(Ab[mr + 8 * ROWPAD + kb + c + 4]));
            }
            #pragma unroll
            for (int nf = 0; nf < 4; nf++) {
                const int nr = (wn * 32 + nf * 8 + g) * ROWPAD;
                bfr[nf][0] = __float_as_uint(to_tf32(Bb[nr + kb + c]));
                bfr[nf][1] = __float_as_uint(to_tf32(Bb[nr + kb + c + 4]));
            }
            #pragma unroll
            for (int mf = 0; mf < 4; mf++)
                #pragma unroll
                for (int nf = 0; nf < 4; nf++)
                    mma_tf32(acc[mf][nf], afr[mf], bfr[nf]);
        }
        __syncthreads();
    }

    // epilogue: bias add + store (float2 per fragment row)
    #pragma unroll
    for (int nf = 0; nf < 4; nf++) {
        const int cb = n0 + wn * 32 + nf * 8 + 2 * c;
        const float bv0 = bias[cb], bv1 = bias[cb + 1];
        #pragma unroll
        for (int mf = 0; mf < 4; mf++) {
            const int r = m0 + wm * 64 + mf * 16 + g;
            float2 v0 = make_float2(acc[mf][nf][0] + bv0, acc[mf][nf][1] + bv1);
            float2 v1 = make_float2(acc[mf][nf][2] + bv0, acc[mf][nf][3] + bv1);
            *(float2*)(C + (size_t)r * N + cb) = v0;
            *(float2*)(C + (size_t)(r + 8) * N + cb) = v1;
        }
    }
}

// ---------------- softmax over each 64-col head chunk; optional row mask ----
// grid = rows, block = 256 (8 warps = 8 head chunks = one full row)
// mask is int32 (harness delivers bool as int32)
__global__ __launch_bounds__(256) void softmax64_kernel(
    float* __restrict__ X, const int* __restrict__ mask)
{
    const int row = blockIdx.x;
    const int h = threadIdx.x >> 5;
    const int lane = threadIdx.x & 31;
    float* p = X + (size_t)row * D_MODEL + h * HDIM;

    if (mask) {
        if (mask[row] == 0) {
            p[lane] = 0.f; p[lane + 32] = 0.f;
            return;
        }
    }
    float v0 = p[lane], v1 = p[lane + 32];
    float m = fmaxf(v0, v1);
    #pragma unroll
    for (int o = 16; o; o >>= 1) m = fmaxf(m, __shfl_xor_sync(0xffffffffu, m, o));
    v0 = expf(v0 - m); v1 = expf(v1 - m);
    float s = v0 + v1;
    #pragma unroll
    for (int o = 16; o; o >>= 1) s += __shfl_xor_sync(0xffffffffu, s, o);
    float inv = 1.f / s;
    p[lane] = v0 * inv; p[lane + 32] = v1 * inv;
}

// ---------------- k_sum: column sum of masked-softmaxed K over s ------------
// grid (b=4, 2 col-strips of 256, 32 row chunks of 128)
__global__ __launch_bounds__(256) void colsum_kernel(int i)
{
    const int b = blockIdx.x;
    const int c = blockIdx.y * 256 + threadIdx.x;
    const int s0 = blockIdx.z * 128;
    const float* p = g_K + ((size_t)b * NI_SEQ + s0) * D_MODEL + c;
    float s = 0.f;
    #pragma unroll 8
    for (int r = 0; r < 128; r++) s += p[(size_t)r * D_MODEL];
    atomicAdd(&g_ksum[(i * B_BATCH + b) * D_MODEL + c], s);
}

// ---------------- kv[i][b][h] = K_h^T @ V_h  (64x64, reduce over ni) --------
// grid (32 = b*h, 8 s-splits of 512), block 256, 4x4 microtile
__global__ __launch_bounds__(256) void kv_kernel(int i)
{
    __shared__ float Ks[32][64];
    __shared__ float Vs[32][64];
    const int bh = blockIdx.x;
    const int b = bh >> 3, h = bh & 7;
    const int s0 = blockIdx.y * 512;
    const int tid = threadIdx.x;
    const int tx = tid & 15, ty = tid >> 4;

    const float* Kbase = g_K + (size_t)b * NI_SEQ * D_MODEL + h * HDIM;
    const float* Vbase = g_V + (size_t)b * NI_SEQ * D_MODEL + h * HDIM;

    float acc[4][4];
    #pragma unroll
    for (int d = 0; d < 4; d++)
        #pragma unroll
        for (int e = 0; e < 4; e++) acc[d][e] = 0.f;

    for (int st = 0; st < 512; st += 32) {
        #pragma unroll
        for (int l = 0; l < 2; l++) {
            int idx = tid + l * 256;          // 0..511 float4 slots
            int r = idx >> 4;
            int c4 = (idx & 15) * 4;
            *(float4*)&Ks[r][c4] = *(const float4*)(Kbase + (size_t)(s0 + st + r) * D_MODEL + c4);
            *(float4*)&Vs[r][c4] = *(const float4*)(Vbase + (size_t)(s0 + st + r) * D_MODEL + c4);
        }
        __syncthreads();
        #pragma unroll 8
        for (int ks = 0; ks < 32; ks++) {
            float a[4], v[4];
            *(float4*)a = *(const float4*)&Ks[ks][ty * 4];
            *(float4*)v = *(const float4*)&Vs[ks][tx * 4];
            #pragma unroll
            for (int d = 0; d < 4; d++)
                #pragma unroll
                for (int e = 0; e < 4; e++)
                    acc[d][e] += a[d] * v[e];
        }
        __syncthreads();
    }
    float* out = g_KV + (size_t)((i * B_BATCH + b) * H_HEADS + h) * (HDIM * HDIM);
    #pragma unroll
    for (int d = 0; d < 4; d++)
        #pragma unroll
        for (int e = 0; e < 4; e++)
            atomicAdd(&out[(ty * 4 + d) * HDIM + tx * 4 + e], acc[d][e]);
}

// ---------------- mix: Q <- (q + sum_i (q @ kv_i) * dinv_i) / 3, in place ---
// dinv_i computed in-kernel from ksum. grid (32 = b*h, 128 row tiles of 64),
// block 256 (16x16, 4x4 microtile)
#define MIX_SMEM_FLOATS (64 * 64 + 3 * 64 * 64 + 64 * 3 + 3 * 64)
__global__ __launch_bounds__(256) void mix_kernel()
{
    extern __shared__ float sm[];
    float* Qs  = sm;                              // [64][64]
    float* kvs = sm + 64 * 64;                    // [3][64][64]
    float* dvs = sm + 64 * 64 + 3 * 64 * 64;      // [64][3]
    float* kss = dvs + 64 * 3;                    // [3][64]

    const int bh = blockIdx.x;
    const int b = bh >> 3, h = bh & 7;
    const int r0 = blockIdx.y * 64;
    const int tid = threadIdx.x;
    const int tx = tid & 15, ty = tid >> 4;

    const size_t qbase = ((size_t)b * N_SEQ + r0) * D_MODEL + h * HDIM;
    #pragma unroll
    for (int l = 0; l < 16; l++) {
        int idx = l * 256 + tid;
        int r = idx >> 6, d = idx & 63;
        Qs[idx] = g_Q[qbase + (size_t)r * D_MODEL + d];
    }
    #pragma unroll
    for (int i = 0; i < 3; i++) {
        const float* src = g_KV + (size_t)((i * B_BATCH + b) * H_HEADS + h) * 4096;
        #pragma unroll
        for (int l = 0; l < 16; l++) {
            int idx = l * 256 + tid;
            kvs[i * 4096 + idx] = src[idx];
        }
    }
    if (tid < 192) {   // [i][d]: i = tid>>6, d = tid&63
        int i = tid >> 6, d = tid & 63;
        kss[tid] = g_ksum[(i * B_BATCH + b) * D_MODEL + h * HDIM + d];
    }
    __syncthreads();

    // compute dinv per row: thread t -> row = t>>2, quarter = t&3 (16 dims each)
    {
        const int r = tid >> 2, qq = tid & 3;
        float p0 = 0.f, p1 = 0.f, p2 = 0.f;
        #pragma unroll
        for (int j = 0; j < 16; j++) {
            int d = qq * 16 + j;
            float qv = Qs[r * 64 + d];
            p0 += qv * kss[d];
            p1 += qv * kss[64 + d];
            p2 += qv * kss[128 + d];
        }
        #pragma unroll
        for (int o = 1; o < 4; o <<= 1) {
            p0 += __shfl_xor_sync(0xffffffffu, p0, o);
            p1 += __shfl_xor_sync(0xffffffffu, p1, o);
            p2 += __shfl_xor_sync(0xffffffffu, p2, o);
        }
        if (qq == 0) {
            dvs[r * 3 + 0] = 1.f / p0;
            dvs[r * 3 + 1] = 1.f / p1;
            dvs[r * 3 + 2] = 1.f / p2;
        }
    }
    __syncthreads();

    float acc[3][4][4];
    #pragma unroll
    for (int i = 0; i < 3; i++)
        #pragma unroll
        for (int jr = 0; jr < 4; jr++)
            #pragma unroll
            for (int je = 0; je < 4; je++) acc[i][jr][je] = 0.f;

    #pragma unroll 4
    for (int d = 0; d < 64; d++) {
        float a[4];
        #pragma unroll
        for (int jr = 0; jr < 4; jr++) a[jr] = Qs[(ty * 4 + jr) * 64 + d];
        #pragma unroll
        for (int i = 0; i < 3; i++) {
            float bv[4];
            *(float4*)bv = *(const float4*)&kvs[i * 4096 + d * 64 + tx * 4];
            #pragma unroll
            for (int jr = 0; jr < 4; jr++) {
                acc[i][jr][0] += a[jr] * bv[0];
                acc[i][jr][1] += a[jr] * bv[1];
                acc[i][jr][2] += a[jr] * bv[2];
                acc[i][jr][3] += a[jr] * bv[3];
            }
        }
    }

    const float third = 1.f / 3.f;
    #pragma unroll
    for (int jr = 0; jr < 4; jr++) {
        int r = ty * 4 + jr;
        #pragma unroll
        for (int je = 0; je < 4; je++) {
            int e = tx * 4 + je;
            float y = Qs[r * 64 + e];
            #pragma unroll
            for (int i = 0; i < 3; i++) y += acc[i][jr][je] * dvs[r * 3 + i];
            g_Q[qbase + (size_t)r * D_MODEL + e] = y * third;
        }
    }
}

// ---------------- launcher --------------------------------------------------
extern "C" void kernel_launch(void* const* d_in, const int* in_sizes, int n_in,
                              void* d_out, int out_size)
{
    const float* x    = (const float*)d_in[0];
    const float* emb[3] = { (const float*)d_in[1], (const float*)d_in[2], (const float*)d_in[3] };
    const float* Wq = (const float*)d_in[4];
    const float* bq = (const float*)d_in[5];
    const float* Wk = (const float*)d_in[6];
    const float* bk = (const float*)d_in[7];
    const float* Wv = (const float*)d_in[8];
    const float* bv = (const float*)d_in[9];
    const float* Wo = (const float*)d_in[10];
    const float* bo = (const float*)d_in[11];
    const int* mask[3] = { (const int*)d_in[12], (const int*)d_in[13],
                           (const int*)d_in[14] };
    float* out = (float*)d_out;

    float *Qb = nullptr, *Kb = nullptr, *Vb = nullptr;
    cudaGetSymbolAddress((void**)&Qb, g_Q);
    cudaGetSymbolAddress((void**)&Kb, g_K);
    cudaGetSymbolAddress((void**)&Vb, g_V);
    cudaFuncSetAttribute(mix_kernel, cudaFuncAttributeMaxDynamicSharedMemorySize,
                         MIX_SMEM_FLOATS * sizeof(float));
    cudaFuncSetAttribute(tf32gemm_nt_bias, cudaFuncAttributeMaxDynamicSharedMemorySize,
                         GEMM_SMEM_BYTES);

    zero_small_kernel<<<1536, 256>>>();

    // Q = softmax64(x @ Wq^T + bq)
    tf32gemm_nt_bias<<<dim3(4, 256), 256, GEMM_SMEM_BYTES>>>(x, Wq, bq, Qb, NQ_ROWS, D_MODEL, D_MODEL);
    softmax64_kernel<<<NQ_ROWS, 256>>>(Qb, nullptr);

    for (int i = 0; i < 3; i++) {
        tf32gemm_nt_bias<<<dim3(4, 128), 256, GEMM_SMEM_BYTES>>>(
            emb[i], Wk + (size_t)i * D_MODEL * D_MODEL,
            bk + i * D_MODEL, Kb, NK_ROWS, D_MODEL, D_MODEL);
        softmax64_kernel<<<NK_ROWS, 256>>>(Kb, mask[i]);
        tf32gemm_nt_bias<<<dim3(4, 128), 256, GEMM_SMEM_BYTES>>>(
            emb[i], Wv + (size_t)i * D_MODEL * D_MODEL,
            bv + i * D_MODEL, Vb, NK_ROWS, D_MODEL, D_MODEL);
        colsum_kernel<<<dim3(4, 2, 32), 256>>>(i);
        kv_kernel<<<dim3(32, 8), 256>>>(i);
    }

    mix_kernel<<<dim3(32, 128), 256, MIX_SMEM_FLOATS * sizeof(float)>>>();

    // out = mixed @ Wo^T + bo
    tf32gemm_nt_bias<<<dim3(4, 256), 256, GEMM_SMEM_BYTES>>>(Qb, Wo, bo, out, NQ_ROWS, D_MODEL, D_MODEL);
}